// round 11
// baseline (speedup 1.0000x reference)
#include <cuda_runtime.h>
#include <cuda_bf16.h>
#include <math.h>
#include <stdint.h>

#define NN 4096
#define NEG_INF -1e9f
#define L2E 1.4426950408889634f

// ---------------- scratch ----------------
__device__ __align__(16) float g_mask[(size_t)NN * NN];
__device__ __align__(16) float g_NW[(size_t)NN * 512];
__device__ __align__(16) unsigned short g_Whi[(size_t)256 * NN];   // bf16 rn(W^T * inv)
__device__ __align__(16) float g_ab[NN * 8];
__device__ __align__(16) float g_W512[128 * 512];
__device__ __align__(16) float g_Wab[128 * 8];
__device__ __align__(16) float g_den[NN * 4];
__device__ __align__(16) float g_inv[NN * 4];
__device__ __align__(16) float g_part[2][(size_t)NN * 256];

__device__ __forceinline__ uint32_t smem_u32(const void* p) {
    uint32_t a;
    asm("{ .reg .u64 tmp; cvta.to.shared.u64 tmp, %1; cvt.u32.u64 %0, tmp; }" : "=r"(a) : "l"(p));
    return a;
}
__device__ __forceinline__ void mma_bf16(float* d, const uint32_t* a, uint32_t b0, uint32_t b1) {
    asm volatile(
        "mma.sync.aligned.m16n8k16.row.col.f32.bf16.bf16.f32 "
        "{%0,%1,%2,%3}, {%4,%5,%6,%7}, {%8,%9}, {%0,%1,%2,%3};"
        : "+f"(d[0]), "+f"(d[1]), "+f"(d[2]), "+f"(d[3])
        : "r"(a[0]), "r"(a[1]), "r"(a[2]), "r"(a[3]), "r"(b0), "r"(b1));
}
#define LDSM4(r, a) asm volatile("ldmatrix.sync.aligned.m8n8.x4.shared.b16 {%0,%1,%2,%3}, [%4];" \
    : "=r"((r)[0]), "=r"((r)[1]), "=r"((r)[2]), "=r"((r)[3]) : "r"(a))
__device__ __forceinline__ void cp_async16(uint32_t dst, const void* src) {
    asm volatile("cp.async.ca.shared.global [%0], [%1], 16;" :: "r"(dst), "l"(src));
}
#define CP_COMMIT()  asm volatile("cp.async.commit_group;" ::: "memory")
#define CP_WAIT(n)   asm volatile("cp.async.wait_group %0;" :: "n"(n) : "memory")

// ---------------- K_prep ----------------
__global__ void k_prep(const float* __restrict__ pp, const float* __restrict__ ssrc,
                       const float* __restrict__ stgt, const float* __restrict__ skw) {
    int idx = blockIdx.x * 256 + threadIdx.x;
    if (idx < 128 * 512) {
        int f = idx >> 9, c = idx & 511;
        float v;
        if (c < 256) { int h = c >> 6, o = c & 63; v = pp[h * 128 * 64 + f * 64 + o]; }
        else         { int cc = c - 256;           v = skw[cc * 128 + f]; }
        g_W512[f * 512 + c] = v;
    }
    if (idx < 128 * 8) {
        int f = idx >> 3, c = idx & 7;
        int h = c & 3;
        const float* sc = (c < 4) ? ssrc : stgt;
        float acc = 0.f;
        #pragma unroll
        for (int o = 0; o < 64; ++o) acc += pp[h * 128 * 64 + f * 64 + o] * sc[h * 64 + o];
        g_Wab[f * 8 + c] = acc;
    }
    if (idx < NN * 4) g_den[idx] = 0.f;
}

// ---------------- K0b: NW = nodes @ W512 ----------------
__global__ void __launch_bounds__(256) k_gemm_nw(const float* __restrict__ nodes) {
    __shared__ float sN[32][128];
    __shared__ float sW[32][128];
    int t = threadIdx.x;
    int r0 = blockIdx.x * 32;
    int c0 = blockIdx.y * 128;
    #pragma unroll
    for (int k = 0; k < 16; ++k) {
        int e = t + k * 256; int kk = e & 127, rr = e >> 7;
        sN[rr][kk] = nodes[(r0 + rr) * 128 + kk];
    }
    float acc[4][4] = {};
    int rg = t >> 5, cg = t & 31;
    for (int kc = 0; kc < 4; ++kc) {
        __syncthreads();
        #pragma unroll
        for (int k = 0; k < 16; ++k) {
            int e = t + k * 256; int cc = e & 127, kk = e >> 7;
            sW[kk][cc] = g_W512[(kc * 32 + kk) * 512 + c0 + cc];
        }
        __syncthreads();
        #pragma unroll
        for (int k = 0; k < 32; ++k) {
            float4 b = *(const float4*)&sW[k][cg * 4];
            #pragma unroll
            for (int q = 0; q < 4; ++q) {
                float a = sN[rg * 4 + q][kc * 32 + k];
                acc[q][0] += a * b.x; acc[q][1] += a * b.y;
                acc[q][2] += a * b.z; acc[q][3] += a * b.w;
            }
        }
    }
    #pragma unroll
    for (int q = 0; q < 4; ++q) {
        *(float4*)&g_NW[(size_t)(r0 + rg * 4 + q) * 512 + c0 + cg * 4] =
            make_float4(acc[q][0], acc[q][1], acc[q][2], acc[q][3]);
    }
}

// ---------------- K0c ----------------
__global__ void k_ab(const float* __restrict__ nodes) {
    int idx = blockIdx.x * 256 + threadIdx.x;
    int n = idx >> 3, c = idx & 7;
    float acc = 0.f;
    #pragma unroll 8
    for (int f = 0; f < 128; ++f) acc += __ldg(&nodes[n * 128 + f]) * g_Wab[f * 8 + c];
    g_ab[idx] = acc;
}

// ---------------- K_A: R6 config (scalar, grid 16x64, 41us measured) ----------------
__global__ void __launch_bounds__(256) k_passA(const float* __restrict__ deg,
                                               const float* __restrict__ bond,
                                               const float* __restrict__ cutp) {
    __shared__ float4 sa[64];
    int t = threadIdx.x;
    int j = blockIdx.x * 256 + t;
    int i0 = blockIdx.y * 64;
    float cut = cutp[0];
    float4 b4 = *(const float4*)&g_ab[j * 8 + 4];
    if (t < 64) sa[t] = *(const float4*)&g_ab[(i0 + t) * 8];
    __syncthreads();
    float d0 = 0.f, d1 = 0.f, d2 = 0.f, d3 = 0.f;
    #pragma unroll 4
    for (int il = 0; il < 64; ++il) {
        size_t off = (size_t)(i0 + il) * NN + j;
        float dd = deg[off], bb = bond[off];
        float wdm = dd + bb;
        float m = (wdm > 0.f) ? wdm : ((bb > cut) ? (bb + wdm) : NEG_INF);
        g_mask[off] = m;
        float4 a = sa[il];
        float x0 = a.x + b4.x; x0 = fmaxf(x0, 0.2f * x0); d0 += __expf(x0 + m);
        float x1 = a.y + b4.y; x1 = fmaxf(x1, 0.2f * x1); d1 += __expf(x1 + m);
        float x2 = a.z + b4.z; x2 = fmaxf(x2, 0.2f * x2); d2 += __expf(x2 + m);
        float x3 = a.w + b4.w; x3 = fmaxf(x3, 0.2f * x3); d3 += __expf(x3 + m);
    }
    atomicAdd(&g_den[j * 4 + 0], d0);
    atomicAdd(&g_den[j * 4 + 1], d1);
    atomicAdd(&g_den[j * 4 + 2], d2);
    atomicAdd(&g_den[j * 4 + 3], d3);
}

__global__ void k_inv() {
    int i = blockIdx.x * 256 + threadIdx.x;
    g_inv[i] = 1.0f / g_den[i];
}

// ---------------- K_T: W^T[hf][j] = rn_bf16(NW[j][hf] * inv[j][h]) ----------------
__global__ void __launch_bounds__(256) k_transp() {
    __shared__ float tile[32][33];
    int t = threadIdx.x;
    int j0 = blockIdx.x * 32, hf0 = blockIdx.y * 32;
    int col = t & 31, rq = t >> 5;
    #pragma unroll
    for (int q = 0; q < 4; ++q) {
        int jj = rq + q * 8;
        int hf = hf0 + col;
        tile[jj][col] = g_NW[(size_t)(j0 + jj) * 512 + hf] * g_inv[(j0 + jj) * 4 + (hf >> 6)];
    }
    __syncthreads();
    #pragma unroll
    for (int q = 0; q < 4; ++q) {
        int jj = rq + q * 8;
        float w = tile[col][jj];
        __nv_bfloat16 b = __float2bfloat16_rn(w);
        g_Whi[(size_t)(hf0 + jj) * NN + j0 + col] = *(unsigned short*)&b;
    }
}

// ---------------- K_LN ----------------
__global__ void __launch_bounds__(256) k_ln(float* __restrict__ outln) {
    __shared__ float red[256];
    __shared__ float red2[256];
    int r = blockIdx.x, t = threadIdx.x;
    const float4* row = (const float4*)&g_mask[(size_t)r * NN];
    float4 v[4];
    float s = 0.f, sq = 0.f;
    #pragma unroll
    for (int k = 0; k < 4; ++k) {
        v[k] = row[t + k * 256];
        s  += v[k].x + v[k].y + v[k].z + v[k].w;
        sq += v[k].x * v[k].x + v[k].y * v[k].y + v[k].z * v[k].z + v[k].w * v[k].w;
    }
    red[t] = s; red2[t] = sq;
    __syncthreads();
    for (int off = 128; off > 0; off >>= 1) {
        if (t < off) { red[t] += red[t + off]; red2[t] += red2[t + off]; }
        __syncthreads();
    }
    float mu  = red[0] * (1.0f / NN);
    float var = red2[0] * (1.0f / NN) - mu * mu;
    float rstd = rsqrtf(var + 1e-5f);
    float4* o = (float4*)&outln[(size_t)r * NN];
    #pragma unroll
    for (int k = 0; k < 4; ++k) {
        float4 w = v[k];
        w.x = (w.x - mu) * rstd; w.y = (w.y - mu) * rstd;
        w.z = (w.z - mu) * rstd; w.w = (w.w - mu) * rstd;
        o[t + k * 256] = w;
    }
}

// ---------------- K_MMA: pipelined HMMA, MUFU/HMMA overlap ----------------
// grid (64 i, 4 head, 2 j-half). 8 warps: fh(2: 32 f) x ih(4: 16 rows).
// smem: sP 2x8KB (double buf) | sW 3x8KB (ring) | sbv 2x64 floats  = ~41KB
#define PBUF 8192
#define WBUF 8192
#define SMEM_MMA (2 * PBUF + 3 * WBUF + 512)

__global__ void __launch_bounds__(256) k_mma(void) {
    extern __shared__ char sm[];
    char* sP = sm;                                    // 2 x 8KB
    float* sbv = (float*)(sm + 2 * PBUF + 3 * WBUF);  // [slot(2)][64]
    uint32_t smP = smem_u32(sm);
    uint32_t smW = smP + 2 * PBUF;

    int t = threadIdx.x;
    int l = t & 31;
    int wid = t >> 5;
    int fh = wid & 1, ih = wid >> 1;
    int head = blockIdx.y;
    int i0 = blockIdx.x * 64;
    int jz = blockIdx.z;
    int jstart = jz * 2048;

    // staging roles: P
    int iloc = t >> 2;             // 0..63
    int jq = (t & 3) * 16;
    float aL = g_ab[(i0 + iloc) * 8 + head];

    // LDSM lane-constant parts
    int lt = l >> 3, lr = l & 7;
    uint32_t swz = (uint32_t)(lr << 4);
    uint32_t aRow0 = (uint32_t)((ih * 16 + lr + (lt & 1) * 8) * 128);
    uint32_t aColT = (uint32_t)(16 * (lt >> 1));
    uint32_t bRow0 = (uint32_t)((fh * 32 + (lt >> 1) * 8 + lr) * 128);
    uint32_t bColT = (uint32_t)(16 * (lt & 1));

    // W cp.async roles: wr = t>>2 row (0..63), 2 x 16B chunks of the 128B row
    int wr = t >> 2;
    int wc0 = (t & 3) * 2;
    const unsigned short* whsrc = &g_Whi[(size_t)(head * 64 + wr) * NN + jstart];
    uint32_t wdstRow = smW + (uint32_t)(wr * 128);
    uint32_t wswz = (uint32_t)((wr & 7) << 4);

    float d[4][4] = {};
    float mv[16];
    uint32_t psw = (uint32_t)((iloc & 7) << 4);
    uint32_t po1 = (uint32_t)(iloc * 128) + ((uint32_t)(2 * jq) ^ psw);
    uint32_t po2 = (uint32_t)(iloc * 128) + ((uint32_t)(2 * jq + 16) ^ psw);
    const float4* mbase = (const float4*)&g_mask[(size_t)(i0 + iloc) * NN + jstart + jq];

    // ---- prologue ----
    {
        #pragma unroll
        for (int q = 0; q < 4; ++q) *(float4*)&mv[q * 4] = mbase[q];     // mask(0)
        if (t < 64) sbv[t] = g_ab[(jstart + t) * 8 + 4 + head];          // b(0) slot0
        #pragma unroll
        for (int q = 0; q < 2; ++q) {
            int c = wc0 + q;
            cp_async16(wdstRow + (((uint32_t)(c * 16)) ^ wswz), whsrc + c * 8);   // W(0) -> ring0
        }
        CP_COMMIT();
        __syncthreads();    // sbv slot0 visible
        // stage P(0) -> sP[0]
        {
            const float* bvec = &sbv[0];
            uint32_t hpp[8];
            #pragma unroll
            for (int q = 0; q < 8; ++q) {
                float2 b2 = *(const float2*)&bvec[jq + q * 2];
                float x0 = aL + b2.x, x1 = aL + b2.y;
                x0 = fmaxf(x0, 0.2f * x0); x1 = fmaxf(x1, 0.2f * x1);
                float e0 = (x0 + mv[q * 2]) * L2E;
                float e1 = (x1 + mv[q * 2 + 1]) * L2E;
                float p0, p1;
                asm("ex2.approx.ftz.f32 %0, %1;" : "=f"(p0) : "f"(e0));
                asm("ex2.approx.ftz.f32 %0, %1;" : "=f"(p1) : "f"(e1));
                asm("cvt.rn.bf16x2.f32 %0, %1, %2;" : "=r"(hpp[q]) : "f"(p1), "f"(p0));
            }
            *(uint4*)(sP + po1) = make_uint4(hpp[0], hpp[1], hpp[2], hpp[3]);
            *(uint4*)(sP + po2) = make_uint4(hpp[4], hpp[5], hpp[6], hpp[7]);
        }
        // prefetch chunk 1
        #pragma unroll
        for (int q = 0; q < 4; ++q) *(float4*)&mv[q * 4] = mbase[16 + q];        // mask(1)
        if (t < 64) sbv[64 + t] = g_ab[(jstart + 64 + t) * 8 + 4 + head];        // b(1) slot1
        #pragma unroll
        for (int q = 0; q < 2; ++q) {
            int c = wc0 + q;
            cp_async16(wdstRow + WBUF + (((uint32_t)(c * 16)) ^ wswz), whsrc + 64 + c * 8);  // W(1) -> ring1
        }
        CP_COMMIT();
        CP_WAIT(1);          // W(0) landed
        __syncthreads();     // sP[0], sbv slot1 visible
    }

    int wring = 0;           // ring index of W(ch)
    for (int ch = 0; ch < 32; ++ch) {
        int pb = ch & 1;
        // ---- (a) stage P(ch+1) -> sP[pb^1]  (MUFU-heavy; overlaps other warps' MMA) ----
        if (ch < 31) {
            const float* bvec = &sbv[(pb ^ 1) * 64];
            uint32_t hpp[8];
            #pragma unroll
            for (int q = 0; q < 8; ++q) {
                float2 b2 = *(const float2*)&bvec[jq + q * 2];
                float x0 = aL + b2.x, x1 = aL + b2.y;
                x0 = fmaxf(x0, 0.2f * x0); x1 = fmaxf(x1, 0.2f * x1);
                float e0 = (x0 + mv[q * 2]) * L2E;
                float e1 = (x1 + mv[q * 2 + 1]) * L2E;
                float p0, p1;
                asm("ex2.approx.ftz.f32 %0, %1;" : "=f"(p0) : "f"(e0));
                asm("ex2.approx.ftz.f32 %0, %1;" : "=f"(p1) : "f"(e1));
                asm("cvt.rn.bf16x2.f32 %0, %1, %2;" : "=r"(hpp[q]) : "f"(p1), "f"(p0));
            }
            char* dst = sP + (pb ^ 1) * PBUF;
            *(uint4*)(dst + po1) = make_uint4(hpp[0], hpp[1], hpp[2], hpp[3]);
            *(uint4*)(dst + po2) = make_uint4(hpp[4], hpp[5], hpp[6], hpp[7]);
        }
        // ---- (b) MMA(ch) from sP[pb], W ring[wring] ----
        {
            uint32_t pbase = smP + (uint32_t)(pb * PBUF);
            uint32_t wbase = smW + (uint32_t)(wring * WBUF);
            #pragma unroll
            for (int kt = 0; kt < 4; ++kt) {
                uint32_t cA = ((uint32_t)(32 * kt) + aColT) ^ swz;
                uint32_t cB = ((uint32_t)(32 * kt) + bColT) ^ swz;
                uint32_t ap[4];
                LDSM4(ap, pbase + aRow0 + cA);
                uint32_t bh0[4], bh1[4];
                LDSM4(bh0, wbase + bRow0 + cB);
                LDSM4(bh1, wbase + bRow0 + 2048 + cB);
                #pragma unroll
                for (int nt = 0; nt < 4; ++nt) {
                    const uint32_t* bh = (nt < 2) ? bh0 : bh1;
                    mma_bf16(d[nt], ap, bh[(nt & 1) * 2], bh[(nt & 1) * 2 + 1]);
                }
            }
        }
        // ---- (c) prefetch chunk ch+2 ----
        if (ch < 30) {
            int nb = ch + 2;
            #pragma unroll
            for (int q = 0; q < 4; ++q) *(float4*)&mv[q * 4] = mbase[nb * 16 + q];
            if (t < 64) sbv[(nb & 1) * 64 + t] = g_ab[(jstart + nb * 64 + t) * 8 + 4 + head];
            int wnext = wring + 2; if (wnext >= 3) wnext -= 3;
            uint32_t wdst = wdstRow + (uint32_t)(wnext * WBUF);
            const unsigned short* wh = whsrc + nb * 64;
            #pragma unroll
            for (int q = 0; q < 2; ++q) {
                int c = wc0 + q;
                cp_async16(wdst + (((uint32_t)(c * 16)) ^ wswz), wh + c * 8);
            }
        }
        CP_COMMIT();
        CP_WAIT(1);
        __syncthreads();
        if (++wring == 3) wring = 0;
    }

    // ---- write partials ----
    #pragma unroll
    for (int nt = 0; nt < 4; ++nt) {
        int gcol = head * 64 + fh * 32 + nt * 8 + (l & 3) * 2;
        #pragma unroll
        for (int rr = 0; rr < 2; ++rr) {
            int row = i0 + ih * 16 + (l >> 2) + rr * 8;
            *(float2*)&g_part[jz][(size_t)row * 256 + gcol] =
                make_float2(d[nt][rr * 2 + 0], d[nt][rr * 2 + 1]);
        }
    }
}

// ---------------- K_EPI: out = elu(part0 + part1 + skip) ----------------
__global__ void __launch_bounds__(256) k_epi(float* __restrict__ out) {
    int id4 = blockIdx.x * 256 + threadIdx.x;
    int row = id4 >> 6;
    int c0 = (id4 & 63) * 4;
    float4 s0 = *(const float4*)&g_part[0][(size_t)row * 256 + c0];
    float4 s1 = *(const float4*)&g_part[1][(size_t)row * 256 + c0];
    float4 sk = *(const float4*)&g_NW[(size_t)row * 512 + 256 + c0];
    float v0 = s0.x + s1.x + sk.x;
    float v1 = s0.y + s1.y + sk.y;
    float v2 = s0.z + s1.z + sk.z;
    float v3 = s0.w + s1.w + sk.w;
    v0 = (v0 > 0.f) ? v0 : expm1f(v0);
    v1 = (v1 > 0.f) ? v1 : expm1f(v1);
    v2 = (v2 > 0.f) ? v2 : expm1f(v2);
    v3 = (v3 > 0.f) ? v3 : expm1f(v3);
    *(float4*)&out[(size_t)row * 256 + c0] = make_float4(v0, v1, v2, v3);
}

// ---------------- launch ----------------
extern "C" void kernel_launch(void* const* d_in, const int* in_sizes, int n_in,
                              void* d_out, int out_size) {
    const float* nodes = (const float*)d_in[0];
    const float* deg   = (const float*)d_in[1];
    const float* bond  = (const float*)d_in[3];
    const float* pp    = (const float*)d_in[4];
    const float* ssrc  = (const float*)d_in[5];
    const float* stgt  = (const float*)d_in[6];
    const float* skw   = (const float*)d_in[7];
    const float* cutp  = (const float*)d_in[8];

    float* out = (float*)d_out;
    float* outln = out + (size_t)NN * 256;

    static int smem_set = 0;
    if (!smem_set) {
        cudaFuncSetAttribute(k_mma, cudaFuncAttributeMaxDynamicSharedMemorySize, SMEM_MMA);
        smem_set = 1;
    }

    k_prep<<<256, 256>>>(pp, ssrc, stgt, skw);
    k_gemm_nw<<<dim3(128, 4), 256>>>(nodes);
    k_ab<<<128, 256>>>(nodes);
    k_passA<<<dim3(16, 64), 256>>>(deg, bond, cutp);
    k_inv<<<64, 256>>>();
    k_transp<<<dim3(128, 8), 256>>>();
    k_ln<<<NN, 256>>>(outln);
    k_mma<<<dim3(64, 4, 2), 256, SMEM_MMA>>>();
    k_epi<<<1024, 256>>>(out);
}

// round 13
// speedup vs baseline: 1.1487x; 1.1487x over previous
#include <cuda_runtime.h>
#include <cuda_bf16.h>
#include <math.h>
#include <stdint.h>

#define NN 4096
#define NEG_INF -1e9f
#define L2E 1.4426950408889634f

// ---------------- scratch ----------------
__device__ __align__(16) float g_mask[(size_t)NN * NN];
__device__ __align__(16) float g_NW[(size_t)NN * 512];
__device__ __align__(16) unsigned short g_Whi[(size_t)256 * NN];   // bf16 rn(W^T * inv)
__device__ __align__(16) float g_ab[NN * 8];
__device__ __align__(16) float g_W512[128 * 512];
__device__ __align__(16) float g_Wab[128 * 8];
__device__ __align__(16) float g_den[NN * 4];
__device__ __align__(16) float g_inv[NN * 4];
__device__ __align__(16) float g_part[4][(size_t)NN * 256];

__device__ __forceinline__ uint32_t smem_u32(const void* p) {
    uint32_t a;
    asm("{ .reg .u64 tmp; cvta.to.shared.u64 tmp, %1; cvt.u32.u64 %0, tmp; }" : "=r"(a) : "l"(p));
    return a;
}
__device__ __forceinline__ void mma_bf16(float* d, const uint32_t* a, uint32_t b0, uint32_t b1) {
    asm volatile(
        "mma.sync.aligned.m16n8k16.row.col.f32.bf16.bf16.f32 "
        "{%0,%1,%2,%3}, {%4,%5,%6,%7}, {%8,%9}, {%0,%1,%2,%3};"
        : "+f"(d[0]), "+f"(d[1]), "+f"(d[2]), "+f"(d[3])
        : "r"(a[0]), "r"(a[1]), "r"(a[2]), "r"(a[3]), "r"(b0), "r"(b1));
}
#define LDSM4(r, a) asm volatile("ldmatrix.sync.aligned.m8n8.x4.shared.b16 {%0,%1,%2,%3}, [%4];" \
    : "=r"((r)[0]), "=r"((r)[1]), "=r"((r)[2]), "=r"((r)[3]) : "r"(a))
__device__ __forceinline__ void cp_async16(uint32_t dst, const void* src) {
    asm volatile("cp.async.ca.shared.global [%0], [%1], 16;" :: "r"(dst), "l"(src));
}
#define CP_COMMIT()  asm volatile("cp.async.commit_group;" ::: "memory")
#define CP_WAIT(n)   asm volatile("cp.async.wait_group %0;" :: "n"(n) : "memory")

// ---------------- K_prep ----------------
__global__ void k_prep(const float* __restrict__ pp, const float* __restrict__ ssrc,
                       const float* __restrict__ stgt, const float* __restrict__ skw) {
    int idx = blockIdx.x * 256 + threadIdx.x;
    if (idx < 128 * 512) {
        int f = idx >> 9, c = idx & 511;
        float v;
        if (c < 256) { int h = c >> 6, o = c & 63; v = pp[h * 128 * 64 + f * 64 + o]; }
        else         { int cc = c - 256;           v = skw[cc * 128 + f]; }
        g_W512[f * 512 + c] = v;
    }
    if (idx < 128 * 8) {
        int f = idx >> 3, c = idx & 7;
        int h = c & 3;
        const float* sc = (c < 4) ? ssrc : stgt;
        float acc = 0.f;
        #pragma unroll
        for (int o = 0; o < 64; ++o) acc += pp[h * 128 * 64 + f * 64 + o] * sc[h * 64 + o];
        g_Wab[f * 8 + c] = acc;
    }
    if (idx < NN * 4) g_den[idx] = 0.f;
}

// ---------------- K0b: NW = nodes @ W512 ----------------
__global__ void __launch_bounds__(256) k_gemm_nw(const float* __restrict__ nodes) {
    __shared__ float sN[32][128];
    __shared__ float sW[32][128];
    int t = threadIdx.x;
    int r0 = blockIdx.x * 32;
    int c0 = blockIdx.y * 128;
    #pragma unroll
    for (int k = 0; k < 16; ++k) {
        int e = t + k * 256; int kk = e & 127, rr = e >> 7;
        sN[rr][kk] = nodes[(r0 + rr) * 128 + kk];
    }
    float acc[4][4] = {};
    int rg = t >> 5, cg = t & 31;
    for (int kc = 0; kc < 4; ++kc) {
        __syncthreads();
        #pragma unroll
        for (int k = 0; k < 16; ++k) {
            int e = t + k * 256; int cc = e & 127, kk = e >> 7;
            sW[kk][cc] = g_W512[(kc * 32 + kk) * 512 + c0 + cc];
        }
        __syncthreads();
        #pragma unroll
        for (int k = 0; k < 32; ++k) {
            float4 b = *(const float4*)&sW[k][cg * 4];
            #pragma unroll
            for (int q = 0; q < 4; ++q) {
                float a = sN[rg * 4 + q][kc * 32 + k];
                acc[q][0] += a * b.x; acc[q][1] += a * b.y;
                acc[q][2] += a * b.z; acc[q][3] += a * b.w;
            }
        }
    }
    #pragma unroll
    for (int q = 0; q < 4; ++q) {
        *(float4*)&g_NW[(size_t)(r0 + rg * 4 + q) * 512 + c0 + cg * 4] =
            make_float4(acc[q][0], acc[q][1], acc[q][2], acc[q][3]);
    }
}

// ---------------- K0c ----------------
__global__ void k_ab(const float* __restrict__ nodes) {
    int idx = blockIdx.x * 256 + threadIdx.x;
    int n = idx >> 3, c = idx & 7;
    float acc = 0.f;
    #pragma unroll 8
    for (int f = 0; f < 128; ++f) acc += __ldg(&nodes[n * 128 + f]) * g_Wab[f * 8 + c];
    g_ab[idx] = acc;
}

// ---------------- K_A: R6 config (scalar, grid 16x64, 41us measured) ----------------
__global__ void __launch_bounds__(256) k_passA(const float* __restrict__ deg,
                                               const float* __restrict__ bond,
                                               const float* __restrict__ cutp) {
    __shared__ float4 sa[64];
    int t = threadIdx.x;
    int j = blockIdx.x * 256 + t;
    int i0 = blockIdx.y * 64;
    float cut = cutp[0];
    float4 b4 = *(const float4*)&g_ab[j * 8 + 4];
    if (t < 64) sa[t] = *(const float4*)&g_ab[(i0 + t) * 8];
    __syncthreads();
    float d0 = 0.f, d1 = 0.f, d2 = 0.f, d3 = 0.f;
    #pragma unroll 4
    for (int il = 0; il < 64; ++il) {
        size_t off = (size_t)(i0 + il) * NN + j;
        float dd = deg[off], bb = bond[off];
        float wdm = dd + bb;
        float m = (wdm > 0.f) ? wdm : ((bb > cut) ? (bb + wdm) : NEG_INF);
        g_mask[off] = m;
        float4 a = sa[il];
        float x0 = a.x + b4.x; x0 = fmaxf(x0, 0.2f * x0); d0 += __expf(x0 + m);
        float x1 = a.y + b4.y; x1 = fmaxf(x1, 0.2f * x1); d1 += __expf(x1 + m);
        float x2 = a.z + b4.z; x2 = fmaxf(x2, 0.2f * x2); d2 += __expf(x2 + m);
        float x3 = a.w + b4.w; x3 = fmaxf(x3, 0.2f * x3); d3 += __expf(x3 + m);
    }
    atomicAdd(&g_den[j * 4 + 0], d0);
    atomicAdd(&g_den[j * 4 + 1], d1);
    atomicAdd(&g_den[j * 4 + 2], d2);
    atomicAdd(&g_den[j * 4 + 3], d3);
}

__global__ void k_inv() {
    int i = blockIdx.x * 256 + threadIdx.x;
    g_inv[i] = 1.0f / g_den[i];
}

// ---------------- K_T: W^T[hf][j] = rn_bf16(NW[j][hf] * inv[j][h]) ----------------
__global__ void __launch_bounds__(256) k_transp() {
    __shared__ float tile[32][33];
    int t = threadIdx.x;
    int j0 = blockIdx.x * 32, hf0 = blockIdx.y * 32;
    int col = t & 31, rq = t >> 5;
    #pragma unroll
    for (int q = 0; q < 4; ++q) {
        int jj = rq + q * 8;
        int hf = hf0 + col;
        tile[jj][col] = g_NW[(size_t)(j0 + jj) * 512 + hf] * g_inv[(j0 + jj) * 4 + (hf >> 6)];
    }
    __syncthreads();
    #pragma unroll
    for (int q = 0; q < 4; ++q) {
        int jj = rq + q * 8;
        float w = tile[col][jj];
        __nv_bfloat16 b = __float2bfloat16_rn(w);
        g_Whi[(size_t)(hf0 + jj) * NN + j0 + col] = *(unsigned short*)&b;
    }
}

// ---------------- K_LN ----------------
__global__ void __launch_bounds__(256) k_ln(float* __restrict__ outln) {
    __shared__ float red[256];
    __shared__ float red2[256];
    int r = blockIdx.x, t = threadIdx.x;
    const float4* row = (const float4*)&g_mask[(size_t)r * NN];
    float4 v[4];
    float s = 0.f, sq = 0.f;
    #pragma unroll
    for (int k = 0; k < 4; ++k) {
        v[k] = row[t + k * 256];
        s  += v[k].x + v[k].y + v[k].z + v[k].w;
        sq += v[k].x * v[k].x + v[k].y * v[k].y + v[k].z * v[k].z + v[k].w * v[k].w;
    }
    red[t] = s; red2[t] = sq;
    __syncthreads();
    for (int off = 128; off > 0; off >>= 1) {
        if (t < off) { red[t] += red[t + off]; red2[t] += red2[t + off]; }
        __syncthreads();
    }
    float mu  = red[0] * (1.0f / NN);
    float var = red2[0] * (1.0f / NN) - mu * mu;
    float rstd = rsqrtf(var + 1e-5f);
    float4* o = (float4*)&outln[(size_t)r * NN];
    #pragma unroll
    for (int k = 0; k < 4; ++k) {
        float4 w = v[k];
        w.x = (w.x - mu) * rstd; w.y = (w.y - mu) * rstd;
        w.z = (w.z - mu) * rstd; w.w = (w.w - mu) * rstd;
        o[t + k * 256] = w;
    }
}

// ---------------- K_MMA: HMMA, all 4 heads per CTA (mask read once) ----------------
// grid (64 i, 4 jseg) = 256 CTAs, 512 threads (16 warps).
// warp tile 32i x 32f of one head: ih = wid>>3, hd = (wid>>1)&3, fh = wid&1.
// smem: sP 4x8KB (heads) | sW 2 x 32KB (cp.async dbuf, 256 rows x 128B) | sbv 2x4x64 f.
#define PBUF_ALL 32768
#define WBUF_ALL 32768
#define SMEM_MMA (PBUF_ALL + 2 * WBUF_ALL + 2048)

__global__ void __launch_bounds__(512) k_mma(void) {
    extern __shared__ char sm[];
    char* sP = sm;                                          // 4 heads x 8KB
    float* sbv = (float*)(sm + PBUF_ALL + 2 * WBUF_ALL);    // [slot(2)][head(4)][64]
    uint32_t smP = smem_u32(sm);
    uint32_t smW = smP + PBUF_ALL;

    int t = threadIdx.x;
    int l = t & 31;
    int wid = t >> 5;
    int ih = wid >> 3, hd = (wid >> 1) & 3, fh = wid & 1;
    int i0 = blockIdx.x * 64;
    int jz = blockIdx.y;
    int jstart = jz * 1024;

    // staging roles: P — iloc row, 8 j, all 4 heads
    int iloc = t >> 3;             // 0..63
    int jq8 = (t & 7) * 8;         // 8 j
    float4 aL4 = *(const float4*)&g_ab[(i0 + iloc) * 8];
    float aLv[4] = { aL4.x, aL4.y, aL4.z, aL4.w };

    // LDSM lane-constant parts
    int lt = l >> 3, lr = l & 7;
    uint32_t swz = (uint32_t)(lr << 4);
    uint32_t aRow0 = (uint32_t)((ih * 32 + lr + (lt & 1) * 8) * 128);
    uint32_t aColT = (uint32_t)(16 * (lt >> 1));
    uint32_t bRow0 = (uint32_t)((fh * 32 + (lt >> 1) * 8 + lr) * 128);
    uint32_t bColT = (uint32_t)(16 * (lt & 1));
    uint32_t pbaseW = smP + (uint32_t)(hd * 8192);

    // W cp.async roles: row = t>>1 (0..255 = head*64+f), 64B (4 x 16B) per thread
    int wrow = t >> 1;
    int wbc0 = (t & 1) * 64;       // byte col base within 128B row
    const unsigned short* whsrc = &g_Whi[(size_t)wrow * NN + jstart];
    uint32_t wdstRow = (uint32_t)(wrow * 128);
    uint32_t wswz = (uint32_t)((wrow & 7) << 4);

    float d[2][4][4] = {};
    float mv[8];
    uint32_t po = (uint32_t)(iloc * 128) + (((uint32_t)(jq8 * 2)) ^ ((uint32_t)((iloc & 7) << 4)));
    const float4* mbase = (const float4*)&g_mask[(size_t)(i0 + iloc) * NN + jstart + jq8];
    // chunk ch offset from mbase: ch*64 floats = ch*16 float4s

    // ---- prologue: mask(0), b(0) slot0, W(0) -> buf0 ----
    {
        *(float4*)&mv[0] = mbase[0];
        *(float4*)&mv[4] = mbase[1];
        if (t < 64) {
            float4 bt = *(const float4*)&g_ab[(jstart + t) * 8 + 4];
            sbv[0 * 256 + 0 * 64 + t] = bt.x;
            sbv[0 * 256 + 1 * 64 + t] = bt.y;
            sbv[0 * 256 + 2 * 64 + t] = bt.z;
            sbv[0 * 256 + 3 * 64 + t] = bt.w;
        }
        #pragma unroll
        for (int q = 0; q < 4; ++q) {
            uint32_t bc = (uint32_t)(wbc0 + q * 16);
            cp_async16(smW + wdstRow + (bc ^ wswz), whsrc + (wbc0 >> 1) + q * 8);
        }
        CP_COMMIT();
        CP_WAIT(0);
        __syncthreads();
    }

    for (int ch = 0; ch < 16; ++ch) {
        int slot = ch & 1;
        int wb = ch & 1;
        // ---- stage P(ch): exp for 4 heads from one mask read ----
        {
            #pragma unroll
            for (int hh = 0; hh < 4; ++hh) {
                const float* bvec = &sbv[slot * 256 + hh * 64 + jq8];
                float a = aLv[hh];
                uint32_t hpp[4];
                #pragma unroll
                for (int q = 0; q < 4; ++q) {
                    float b0 = bvec[q * 2], b1 = bvec[q * 2 + 1];
                    float x0 = a + b0, x1 = a + b1;
                    x0 = fmaxf(x0, 0.2f * x0); x1 = fmaxf(x1, 0.2f * x1);
                    float e0 = (x0 + mv[q * 2]) * L2E;
                    float e1 = (x1 + mv[q * 2 + 1]) * L2E;
                    float p0, p1;
                    asm("ex2.approx.ftz.f32 %0, %1;" : "=f"(p0) : "f"(e0));
                    asm("ex2.approx.ftz.f32 %0, %1;" : "=f"(p1) : "f"(e1));
                    asm("cvt.rn.bf16x2.f32 %0, %1, %2;" : "=r"(hpp[q]) : "f"(p1), "f"(p0));
                }
                *(uint4*)(sP + hh * 8192 + po) = make_uint4(hpp[0], hpp[1], hpp[2], hpp[3]);
            }
        }
        // ---- prefetch chunk ch+1 ----
        if (ch < 15) {
            *(float4*)&mv[0] = mbase[(ch + 1) * 16];
            *(float4*)&mv[4] = mbase[(ch + 1) * 16 + 1];
            if (t < 64) {
                float4 bt = *(const float4*)&g_ab[(jstart + (ch + 1) * 64 + t) * 8 + 4];
                float* sb = &sbv[(slot ^ 1) * 256];
                sb[0 * 64 + t] = bt.x; sb[1 * 64 + t] = bt.y;
                sb[2 * 64 + t] = bt.z; sb[3 * 64 + t] = bt.w;
            }
            uint32_t wdst = smW + (uint32_t)((wb ^ 1) * WBUF_ALL) + wdstRow;
            const unsigned short* wh = whsrc + (ch + 1) * 64 + (wbc0 >> 1);
            #pragma unroll
            for (int q = 0; q < 4; ++q) {
                uint32_t bc = (uint32_t)(wbc0 + q * 16);
                cp_async16(wdst + (bc ^ wswz), wh + q * 8);
            }
        }
        CP_COMMIT();
        CP_WAIT(1);
        __syncthreads();
        // ---- MMA(ch): warp = 32i x 32f of head hd ----
        {
            uint32_t wbase = smW + (uint32_t)(wb * WBUF_ALL) + (uint32_t)(hd * 8192);
            #pragma unroll
            for (int kt = 0; kt < 4; ++kt) {
                uint32_t cA = ((uint32_t)(32 * kt) + aColT) ^ swz;
                uint32_t cB = ((uint32_t)(32 * kt) + bColT) ^ swz;
                uint32_t ap0[4], ap1[4];
                LDSM4(ap0, pbaseW + aRow0 + cA);
                LDSM4(ap1, pbaseW + aRow0 + 2048 + cA);
                uint32_t bh0[4], bh1[4];
                LDSM4(bh0, wbase + bRow0 + cB);
                LDSM4(bh1, wbase + bRow0 + 2048 + cB);
                #pragma unroll
                for (int nt = 0; nt < 4; ++nt) {
                    const uint32_t* bh = (nt < 2) ? bh0 : bh1;
                    uint32_t b0 = bh[(nt & 1) * 2], b1 = bh[(nt & 1) * 2 + 1];
                    mma_bf16(d[0][nt], ap0, b0, b1);
                    mma_bf16(d[1][nt], ap1, b0, b1);
                }
            }
        }
        __syncthreads();
    }

    // ---- write partials ----
    #pragma unroll
    for (int mt = 0; mt < 2; ++mt) {
        #pragma unroll
        for (int nt = 0; nt < 4; ++nt) {
            int gcol = hd * 64 + fh * 32 + nt * 8 + (l & 3) * 2;
            #pragma unroll
            for (int rr = 0; rr < 2; ++rr) {
                int row = i0 + ih * 32 + mt * 16 + (l >> 2) + rr * 8;
                *(float2*)&g_part[jz][(size_t)row * 256 + gcol] =
                    make_float2(d[mt][nt][rr * 2 + 0], d[mt][nt][rr * 2 + 1]);
            }
        }
    }
}

// ---------------- K_EPI: out = elu(sum parts + skip) ----------------
__global__ void __launch_bounds__(256) k_epi(float* __restrict__ out) {
    int id4 = blockIdx.x * 256 + threadIdx.x;
    int row = id4 >> 6;
    int c0 = (id4 & 63) * 4;
    float4 s0 = *(const float4*)&g_part[0][(size_t)row * 256 + c0];
    float4 s1 = *(const float4*)&g_part[1][(size_t)row * 256 + c0];
    float4 s2 = *(const float4*)&g_part[2][(size_t)row * 256 + c0];
    float4 s3 = *(const float4*)&g_part[3][(size_t)row * 256 + c0];
    float4 sk = *(const float4*)&g_NW[(size_t)row * 512 + 256 + c0];
    float v0 = s0.x + s1.x + s2.x + s3.x + sk.x;
    float v1 = s0.y + s1.y + s2.y + s3.y + sk.y;
    float v2 = s0.z + s1.z + s2.z + s3.z + sk.z;
    float v3 = s0.w + s1.w + s2.w + s3.w + sk.w;
    v0 = (v0 > 0.f) ? v0 : expm1f(v0);
    v1 = (v1 > 0.f) ? v1 : expm1f(v1);
    v2 = (v2 > 0.f) ? v2 : expm1f(v2);
    v3 = (v3 > 0.f) ? v3 : expm1f(v3);
    *(float4*)&out[(size_t)row * 256 + c0] = make_float4(v0, v1, v2, v3);
}

// ---------------- launch ----------------
extern "C" void kernel_launch(void* const* d_in, const int* in_sizes, int n_in,
                              void* d_out, int out_size) {
    const float* nodes = (const float*)d_in[0];
    const float* deg   = (const float*)d_in[1];
    const float* bond  = (const float*)d_in[3];
    const float* pp    = (const float*)d_in[4];
    const float* ssrc  = (const float*)d_in[5];
    const float* stgt  = (const float*)d_in[6];
    const float* skw   = (const float*)d_in[7];
    const float* cutp  = (const float*)d_in[8];

    float* out = (float*)d_out;
    float* outln = out + (size_t)NN * 256;

    static int smem_set = 0;
    if (!smem_set) {
        cudaFuncSetAttribute(k_mma, cudaFuncAttributeMaxDynamicSharedMemorySize, SMEM_MMA);
        smem_set = 1;
    }

    k_prep<<<256, 256>>>(pp, ssrc, stgt, skw);
    k_gemm_nw<<<dim3(128, 4), 256>>>(nodes);
    k_ab<<<128, 256>>>(nodes);
    k_passA<<<dim3(16, 64), 256>>>(deg, bond, cutp);
    k_inv<<<64, 256>>>();
    k_transp<<<dim3(128, 8), 256>>>();
    k_ln<<<NN, 256>>>(outln);
    k_mma<<<dim3(64, 4), 512, SMEM_MMA>>>();
    k_epi<<<1024, 256>>>(out);
}

// round 14
// speedup vs baseline: 1.2149x; 1.0576x over previous
#include <cuda_runtime.h>
#include <cuda_bf16.h>
#include <math.h>
#include <stdint.h>

#define NN 4096
#define NEG_INF -1e9f
#define L2E 1.4426950408889634f

// ---------------- scratch ----------------
__device__ __align__(16) float g_mask[(size_t)NN * NN];
__device__ __align__(16) float g_NW[(size_t)NN * 512];
__device__ __align__(16) unsigned short g_Whi[(size_t)256 * NN];   // bf16 rn(W^T * inv)
__device__ __align__(16) float g_ab[NN * 8];
__device__ __align__(16) float g_W512[128 * 512];
__device__ __align__(16) float g_Wab[128 * 8];
__device__ __align__(16) float g_den[NN * 4];
__device__ __align__(16) float g_inv[NN * 4];
__device__ __align__(16) float g_part[4][(size_t)NN * 256];

__device__ __forceinline__ uint32_t smem_u32(const void* p) {
    uint32_t a;
    asm("{ .reg .u64 tmp; cvta.to.shared.u64 tmp, %1; cvt.u32.u64 %0, tmp; }" : "=r"(a) : "l"(p));
    return a;
}
__device__ __forceinline__ void mma_bf16(float* d, const uint32_t* a, uint32_t b0, uint32_t b1) {
    asm volatile(
        "mma.sync.aligned.m16n8k16.row.col.f32.bf16.bf16.f32 "
        "{%0,%1,%2,%3}, {%4,%5,%6,%7}, {%8,%9}, {%0,%1,%2,%3};"
        : "+f"(d[0]), "+f"(d[1]), "+f"(d[2]), "+f"(d[3])
        : "r"(a[0]), "r"(a[1]), "r"(a[2]), "r"(a[3]), "r"(b0), "r"(b1));
}
#define LDSM4(r, a) asm volatile("ldmatrix.sync.aligned.m8n8.x4.shared.b16 {%0,%1,%2,%3}, [%4];" \
    : "=r"((r)[0]), "=r"((r)[1]), "=r"((r)[2]), "=r"((r)[3]) : "r"(a))
__device__ __forceinline__ void cp_async16(uint32_t dst, const void* src) {
    asm volatile("cp.async.ca.shared.global [%0], [%1], 16;" :: "r"(dst), "l"(src));
}
#define CP_COMMIT()  asm volatile("cp.async.commit_group;" ::: "memory")
#define CP_WAIT(n)   asm volatile("cp.async.wait_group %0;" :: "n"(n) : "memory")

// ---------------- K_prep ----------------
__global__ void k_prep(const float* __restrict__ pp, const float* __restrict__ ssrc,
                       const float* __restrict__ stgt, const float* __restrict__ skw) {
    int idx = blockIdx.x * 256 + threadIdx.x;
    if (idx < 128 * 512) {
        int f = idx >> 9, c = idx & 511;
        float v;
        if (c < 256) { int h = c >> 6, o = c & 63; v = pp[h * 128 * 64 + f * 64 + o]; }
        else         { int cc = c - 256;           v = skw[cc * 128 + f]; }
        g_W512[f * 512 + c] = v;
    }
    if (idx < 128 * 8) {
        int f = idx >> 3, c = idx & 7;
        int h = c & 3;
        const float* sc = (c < 4) ? ssrc : stgt;
        float acc = 0.f;
        #pragma unroll
        for (int o = 0; o < 64; ++o) acc += pp[h * 128 * 64 + f * 64 + o] * sc[h * 64 + o];
        g_Wab[f * 8 + c] = acc;
    }
    if (idx < NN * 4) g_den[idx] = 0.f;
}

// ---------------- K0b: NW = nodes @ W512 ----------------
__global__ void __launch_bounds__(256) k_gemm_nw(const float* __restrict__ nodes) {
    __shared__ float sN[32][128];
    __shared__ float sW[32][128];
    int t = threadIdx.x;
    int r0 = blockIdx.x * 32;
    int c0 = blockIdx.y * 128;
    #pragma unroll
    for (int k = 0; k < 16; ++k) {
        int e = t + k * 256; int kk = e & 127, rr = e >> 7;
        sN[rr][kk] = nodes[(r0 + rr) * 128 + kk];
    }
    float acc[4][4] = {};
    int rg = t >> 5, cg = t & 31;
    for (int kc = 0; kc < 4; ++kc) {
        __syncthreads();
        #pragma unroll
        for (int k = 0; k < 16; ++k) {
            int e = t + k * 256; int cc = e & 127, kk = e >> 7;
            sW[kk][cc] = g_W512[(kc * 32 + kk) * 512 + c0 + cc];
        }
        __syncthreads();
        #pragma unroll
        for (int k = 0; k < 32; ++k) {
            float4 b = *(const float4*)&sW[k][cg * 4];
            #pragma unroll
            for (int q = 0; q < 4; ++q) {
                float a = sN[rg * 4 + q][kc * 32 + k];
                acc[q][0] += a * b.x; acc[q][1] += a * b.y;
                acc[q][2] += a * b.z; acc[q][3] += a * b.w;
            }
        }
    }
    #pragma unroll
    for (int q = 0; q < 4; ++q) {
        *(float4*)&g_NW[(size_t)(r0 + rg * 4 + q) * 512 + c0 + cg * 4] =
            make_float4(acc[q][0], acc[q][1], acc[q][2], acc[q][3]);
    }
}

// ---------------- K0c ----------------
__global__ void k_ab(const float* __restrict__ nodes) {
    int idx = blockIdx.x * 256 + threadIdx.x;
    int n = idx >> 3, c = idx & 7;
    float acc = 0.f;
    #pragma unroll 8
    for (int f = 0; f < 128; ++f) acc += __ldg(&nodes[n * 128 + f]) * g_Wab[f * 8 + c];
    g_ab[idx] = acc;
}

// ---------------- K_A: scalar, grid 16x64 (41us measured) ----------------
__global__ void __launch_bounds__(256) k_passA(const float* __restrict__ deg,
                                               const float* __restrict__ bond,
                                               const float* __restrict__ cutp) {
    __shared__ float4 sa[64];
    int t = threadIdx.x;
    int j = blockIdx.x * 256 + t;
    int i0 = blockIdx.y * 64;
    float cut = cutp[0];
    float4 b4 = *(const float4*)&g_ab[j * 8 + 4];
    if (t < 64) sa[t] = *(const float4*)&g_ab[(i0 + t) * 8];
    __syncthreads();
    float d0 = 0.f, d1 = 0.f, d2 = 0.f, d3 = 0.f;
    #pragma unroll 4
    for (int il = 0; il < 64; ++il) {
        size_t off = (size_t)(i0 + il) * NN + j;
        float dd = deg[off], bb = bond[off];
        float wdm = dd + bb;
        float m = (wdm > 0.f) ? wdm : ((bb > cut) ? (bb + wdm) : NEG_INF);
        g_mask[off] = m;
        float4 a = sa[il];
        float x0 = a.x + b4.x; x0 = fmaxf(x0, 0.2f * x0); d0 += __expf(x0 + m);
        float x1 = a.y + b4.y; x1 = fmaxf(x1, 0.2f * x1); d1 += __expf(x1 + m);
        float x2 = a.z + b4.z; x2 = fmaxf(x2, 0.2f * x2); d2 += __expf(x2 + m);
        float x3 = a.w + b4.w; x3 = fmaxf(x3, 0.2f * x3); d3 += __expf(x3 + m);
    }
    atomicAdd(&g_den[j * 4 + 0], d0);
    atomicAdd(&g_den[j * 4 + 1], d1);
    atomicAdd(&g_den[j * 4 + 2], d2);
    atomicAdd(&g_den[j * 4 + 3], d3);
}

__global__ void k_inv() {
    int i = blockIdx.x * 256 + threadIdx.x;
    g_inv[i] = 1.0f / g_den[i];
}

// ---------------- K_T: W^T[hf][j] = rn_bf16(NW[j][hf] * inv[j][h]) ----------------
__global__ void __launch_bounds__(256) k_transp() {
    __shared__ float tile[32][33];
    int t = threadIdx.x;
    int j0 = blockIdx.x * 32, hf0 = blockIdx.y * 32;
    int col = t & 31, rq = t >> 5;
    #pragma unroll
    for (int q = 0; q < 4; ++q) {
        int jj = rq + q * 8;
        int hf = hf0 + col;
        tile[jj][col] = g_NW[(size_t)(j0 + jj) * 512 + hf] * g_inv[(j0 + jj) * 4 + (hf >> 6)];
    }
    __syncthreads();
    #pragma unroll
    for (int q = 0; q < 4; ++q) {
        int jj = rq + q * 8;
        float w = tile[col][jj];
        __nv_bfloat16 b = __float2bfloat16_rn(w);
        g_Whi[(size_t)(hf0 + jj) * NN + j0 + col] = *(unsigned short*)&b;
    }
}

// ---------------- K_LN ----------------
__global__ void __launch_bounds__(256) k_ln(float* __restrict__ outln) {
    __shared__ float red[256];
    __shared__ float red2[256];
    int r = blockIdx.x, t = threadIdx.x;
    const float4* row = (const float4*)&g_mask[(size_t)r * NN];
    float4 v[4];
    float s = 0.f, sq = 0.f;
    #pragma unroll
    for (int k = 0; k < 4; ++k) {
        v[k] = row[t + k * 256];
        s  += v[k].x + v[k].y + v[k].z + v[k].w;
        sq += v[k].x * v[k].x + v[k].y * v[k].y + v[k].z * v[k].z + v[k].w * v[k].w;
    }
    red[t] = s; red2[t] = sq;
    __syncthreads();
    for (int off = 128; off > 0; off >>= 1) {
        if (t < off) { red[t] += red[t + off]; red2[t] += red2[t + off]; }
        __syncthreads();
    }
    float mu  = red[0] * (1.0f / NN);
    float var = red2[0] * (1.0f / NN) - mu * mu;
    float rstd = rsqrtf(var + 1e-5f);
    float4* o = (float4*)&outln[(size_t)r * NN];
    #pragma unroll
    for (int k = 0; k < 4; ++k) {
        float4 w = v[k];
        w.x = (w.x - mu) * rstd; w.y = (w.y - mu) * rstd;
        w.z = (w.z - mu) * rstd; w.w = (w.w - mu) * rstd;
        o[t + k * 256] = w;
    }
}

// ---------------- K_MMA: HMMA, all 4 heads per CTA (mask read once) ----------------
#define PBUF_ALL 32768
#define WBUF_ALL 32768
#define SMEM_MMA (PBUF_ALL + 2 * WBUF_ALL + 2048)

__global__ void __launch_bounds__(512) k_mma(void) {
    extern __shared__ char sm[];
    char* sP = sm;                                          // 4 heads x 8KB
    float* sbv = (float*)(sm + PBUF_ALL + 2 * WBUF_ALL);    // [slot(2)][head(4)][64]
    uint32_t smP = smem_u32(sm);
    uint32_t smW = smP + PBUF_ALL;

    int t = threadIdx.x;
    int l = t & 31;
    int wid = t >> 5;
    int ih = wid >> 3, hd = (wid >> 1) & 3, fh = wid & 1;
    int i0 = blockIdx.x * 64;
    int jz = blockIdx.y;
    int jstart = jz * 1024;

    int iloc = t >> 3;             // 0..63
    int jq8 = (t & 7) * 8;         // 8 j
    float4 aL4 = *(const float4*)&g_ab[(i0 + iloc) * 8];
    float aLv[4] = { aL4.x, aL4.y, aL4.z, aL4.w };

    int lt = l >> 3, lr = l & 7;
    uint32_t swz = (uint32_t)(lr << 4);
    uint32_t aRow0 = (uint32_t)((ih * 32 + lr + (lt & 1) * 8) * 128);
    uint32_t aColT = (uint32_t)(16 * (lt >> 1));
    uint32_t bRow0 = (uint32_t)((fh * 32 + (lt >> 1) * 8 + lr) * 128);
    uint32_t bColT = (uint32_t)(16 * (lt & 1));
    uint32_t pbaseW = smP + (uint32_t)(hd * 8192);

    int wrow = t >> 1;
    int wbc0 = (t & 1) * 64;
    const unsigned short* whsrc = &g_Whi[(size_t)wrow * NN + jstart];
    uint32_t wdstRow = (uint32_t)(wrow * 128);
    uint32_t wswz = (uint32_t)((wrow & 7) << 4);

    float d[2][4][4] = {};
    float mv[8];
    uint32_t po = (uint32_t)(iloc * 128) + (((uint32_t)(jq8 * 2)) ^ ((uint32_t)((iloc & 7) << 4)));
    const float4* mbase = (const float4*)&g_mask[(size_t)(i0 + iloc) * NN + jstart + jq8];

    // ---- prologue ----
    {
        *(float4*)&mv[0] = mbase[0];
        *(float4*)&mv[4] = mbase[1];
        if (t < 64) {
            float4 bt = *(const float4*)&g_ab[(jstart + t) * 8 + 4];
            sbv[0 * 256 + 0 * 64 + t] = bt.x;
            sbv[0 * 256 + 1 * 64 + t] = bt.y;
            sbv[0 * 256 + 2 * 64 + t] = bt.z;
            sbv[0 * 256 + 3 * 64 + t] = bt.w;
        }
        #pragma unroll
        for (int q = 0; q < 4; ++q) {
            uint32_t bc = (uint32_t)(wbc0 + q * 16);
            cp_async16(smW + wdstRow + (bc ^ wswz), whsrc + (wbc0 >> 1) + q * 8);
        }
        CP_COMMIT();
        CP_WAIT(0);
        __syncthreads();
    }

    for (int ch = 0; ch < 16; ++ch) {
        int slot = ch & 1;
        int wb = ch & 1;
        // ---- stage P(ch): exp for 4 heads from one mask read ----
        {
            #pragma unroll
            for (int hh = 0; hh < 4; ++hh) {
                const float* bvec = &sbv[slot * 256 + hh * 64 + jq8];
                float a = aLv[hh];
                uint32_t hpp[4];
                #pragma unroll
                for (int q = 0; q < 4; ++q) {
                    float b0 = bvec[q * 2], b1 = bvec[q * 2 + 1];
                    float x0 = a + b0, x1 = a + b1;
                    x0 = fmaxf(x0, 0.2f * x0); x1 = fmaxf(x1, 0.2f * x1);
                    float e0 = (x0 + mv[q * 2]) * L2E;
                    float e1 = (x1 + mv[q * 2 + 1]) * L2E;
                    float p0, p1;
                    asm("ex2.approx.ftz.f32 %0, %1;" : "=f"(p0) : "f"(e0));
                    asm("ex2.approx.ftz.f32 %0, %1;" : "=f"(p1) : "f"(e1));
                    asm("cvt.rn.bf16x2.f32 %0, %1, %2;" : "=r"(hpp[q]) : "f"(p1), "f"(p0));
                }
                *(uint4*)(sP + hh * 8192 + po) = make_uint4(hpp[0], hpp[1], hpp[2], hpp[3]);
            }
        }
        // ---- prefetch chunk ch+1 ----
        if (ch < 15) {
            *(float4*)&mv[0] = mbase[(ch + 1) * 16];
            *(float4*)&mv[4] = mbase[(ch + 1) * 16 + 1];
            if (t < 64) {
                float4 bt = *(const float4*)&g_ab[(jstart + (ch + 1) * 64 + t) * 8 + 4];
                float* sb = &sbv[(slot ^ 1) * 256];
                sb[0 * 64 + t] = bt.x; sb[1 * 64 + t] = bt.y;
                sb[2 * 64 + t] = bt.z; sb[3 * 64 + t] = bt.w;
            }
            uint32_t wdst = smW + (uint32_t)((wb ^ 1) * WBUF_ALL) + wdstRow;
            const unsigned short* wh = whsrc + (ch + 1) * 64 + (wbc0 >> 1);
            #pragma unroll
            for (int q = 0; q < 4; ++q) {
                uint32_t bc = (uint32_t)(wbc0 + q * 16);
                cp_async16(wdst + (bc ^ wswz), wh + q * 8);
            }
        }
        CP_COMMIT();
        CP_WAIT(1);
        __syncthreads();
        // ---- MMA(ch): warp = 32i x 32f of head hd ----
        {
            uint32_t wbase = smW + (uint32_t)(wb * WBUF_ALL) + (uint32_t)(hd * 8192);
            #pragma unroll
            for (int kt = 0; kt < 4; ++kt) {
                uint32_t cA = ((uint32_t)(32 * kt) + aColT) ^ swz;
                uint32_t cB = ((uint32_t)(32 * kt) + bColT) ^ swz;
                uint32_t ap0[4], ap1[4];
                LDSM4(ap0, pbaseW + aRow0 + cA);
                LDSM4(ap1, pbaseW + aRow0 + 2048 + cA);
                uint32_t bh0[4], bh1[4];
                LDSM4(bh0, wbase + bRow0 + cB);
                LDSM4(bh1, wbase + bRow0 + 2048 + cB);
                #pragma unroll
                for (int nt = 0; nt < 4; ++nt) {
                    const uint32_t* bh = (nt < 2) ? bh0 : bh1;
                    uint32_t b0 = bh[(nt & 1) * 2], b1 = bh[(nt & 1) * 2 + 1];
                    mma_bf16(d[0][nt], ap0, b0, b1);
                    mma_bf16(d[1][nt], ap1, b0, b1);
                }
            }
        }
        __syncthreads();
    }

    // ---- write partials ----
    #pragma unroll
    for (int mt = 0; mt < 2; ++mt) {
        #pragma unroll
        for (int nt = 0; nt < 4; ++nt) {
            int gcol = hd * 64 + fh * 32 + nt * 8 + (l & 3) * 2;
            #pragma unroll
            for (int rr = 0; rr < 2; ++rr) {
                int row = i0 + ih * 32 + mt * 16 + (l >> 2) + rr * 8;
                *(float2*)&g_part[jz][(size_t)row * 256 + gcol] =
                    make_float2(d[mt][nt][rr * 2 + 0], d[mt][nt][rr * 2 + 1]);
            }
        }
    }
}

// ---------------- K_EPI: out = elu(sum parts + skip) ----------------
__global__ void __launch_bounds__(256) k_epi(float* __restrict__ out) {
    int id4 = blockIdx.x * 256 + threadIdx.x;
    int row = id4 >> 6;
    int c0 = (id4 & 63) * 4;
    float4 s0 = *(const float4*)&g_part[0][(size_t)row * 256 + c0];
    float4 s1 = *(const float4*)&g_part[1][(size_t)row * 256 + c0];
    float4 s2 = *(const float4*)&g_part[2][(size_t)row * 256 + c0];
    float4 s3 = *(const float4*)&g_part[3][(size_t)row * 256 + c0];
    float4 sk = *(const float4*)&g_NW[(size_t)row * 512 + 256 + c0];
    float v0 = s0.x + s1.x + s2.x + s3.x + sk.x;
    float v1 = s0.y + s1.y + s2.y + s3.y + sk.y;
    float v2 = s0.z + s1.z + s2.z + s3.z + sk.z;
    float v3 = s0.w + s1.w + s2.w + s3.w + sk.w;
    v0 = (v0 > 0.f) ? v0 : expm1f(v0);
    v1 = (v1 > 0.f) ? v1 : expm1f(v1);
    v2 = (v2 > 0.f) ? v2 : expm1f(v2);
    v3 = (v3 > 0.f) ? v3 : expm1f(v3);
    *(float4*)&out[(size_t)row * 256 + c0] = make_float4(v0, v1, v2, v3);
}

// ---------------- launch: fork/join concurrency ----------------
// deps: prep -> {gemm_nw | ab}; ab -> passA -> inv; {gemm_nw, inv} -> transp -> mma -> epi
//       passA -> ln (independent of transp/mma -> overlap with them)
extern "C" void kernel_launch(void* const* d_in, const int* in_sizes, int n_in,
                              void* d_out, int out_size) {
    const float* nodes = (const float*)d_in[0];
    const float* deg   = (const float*)d_in[1];
    const float* bond  = (const float*)d_in[3];
    const float* pp    = (const float*)d_in[4];
    const float* ssrc  = (const float*)d_in[5];
    const float* stgt  = (const float*)d_in[6];
    const float* skw   = (const float*)d_in[7];
    const float* cutp  = (const float*)d_in[8];

    float* out = (float*)d_out;
    float* outln = out + (size_t)NN * 256;

    static cudaStream_t s2 = 0;
    static cudaEvent_t evP = 0, evG = 0, evA = 0, evL = 0;
    static int init_done = 0;
    if (!init_done) {
        cudaFuncSetAttribute(k_mma, cudaFuncAttributeMaxDynamicSharedMemorySize, SMEM_MMA);
        cudaStreamCreateWithFlags(&s2, cudaStreamNonBlocking);
        cudaEventCreateWithFlags(&evP, cudaEventDisableTiming);
        cudaEventCreateWithFlags(&evG, cudaEventDisableTiming);
        cudaEventCreateWithFlags(&evA, cudaEventDisableTiming);
        cudaEventCreateWithFlags(&evL, cudaEventDisableTiming);
        init_done = 1;
    }

    k_prep<<<256, 256>>>(pp, ssrc, stgt, skw);
    cudaEventRecord(evP, 0);

    // side stream: gemm_nw (overlaps passA)
    cudaStreamWaitEvent(s2, evP, 0);
    k_gemm_nw<<<dim3(128, 4), 256, 0, s2>>>(nodes);
    cudaEventRecord(evG, s2);

    // main stream
    k_ab<<<128, 256>>>(nodes);
    k_passA<<<dim3(16, 64), 256>>>(deg, bond, cutp);
    cudaEventRecord(evA, 0);
    k_inv<<<64, 256>>>();

    // side stream: ln (overlaps transp + mma)
    cudaStreamWaitEvent(s2, evA, 0);
    k_ln<<<NN, 256, 0, s2>>>(outln);
    cudaEventRecord(evL, s2);

    // main stream continues
    cudaStreamWaitEvent(0, evG, 0);
    k_transp<<<dim3(128, 8), 256>>>();
    k_mma<<<dim3(64, 4), 512, SMEM_MMA>>>();
    k_epi<<<1024, 256>>>(out);
    cudaStreamWaitEvent(0, evL, 0);   // join side stream
}